// round 10
// baseline (speedup 1.0000x reference)
#include <cuda_runtime.h>
#include <cuda_fp16.h>
#include <cstdint>

// Problem shape (fixed by dataset)
static constexpr int B_DIM   = 32768;
static constexpr int IN_DIM  = 64;
static constexpr int C_DIM   = 4096;

static constexpr int TM = 128;   // M tile per iteration
static constexpr int M_SUB = 4;  // M iterations per CTA (w tile reused 4x)
static constexpr int TN = 128;   // N tile per CTA
static constexpr int M_TILES = B_DIM / (TM * M_SUB);  // 64
static constexpr int N_TILES = C_DIM / TN;            // 32

// SMEM: A[2] = x fp16 [128 x 64k] double-buffered, B = w fp16 [128 x 64k]
// (column-PERMUTED). Row stride padded to 72 halfs (144 B) -> conflict-free ldmatrix.
static constexpr int KP       = 72;                    // padded K stride (elements)
static constexpr int A_BYTES  = 128 * KP * 2;          // 18432
static constexpr int OFF_XSQ0 = 0;                     // 128 f32
static constexpr int OFF_XSQ1 = 512;                   // 128 f32
static constexpr int OFF_WSQ  = 1024;                  // 128 f32 (GLOBAL col order)
static constexpr int OFF_A0   = 2048;
static constexpr int OFF_A1   = OFF_A0 + A_BYTES;      // 20480
static constexpr int OFF_B    = OFF_A1 + A_BYTES;      // 38912
static constexpr int SMEM_BYTES = OFF_B + A_BYTES;     // 57344

// ---------------- helpers ----------------
__device__ __forceinline__ uint32_t smem_u32(const void* p) {
    uint32_t a;
    asm("{ .reg .u64 t; cvta.to.shared.u64 t, %1; cvt.u32.u64 %0, t; }" : "=r"(a) : "l"(p));
    return a;
}
__device__ __forceinline__ uint32_t pack_h2(float a, float b) {
    __half2 v(__float2half_rn(a), __float2half_rn(b));
    return *reinterpret_cast<uint32_t*>(&v);
}
__device__ __forceinline__ void ldsm_x4(uint32_t* r, uint32_t addr) {
    asm volatile("ldmatrix.sync.aligned.m8n8.x4.shared.b16 {%0,%1,%2,%3}, [%4];"
                 : "=r"(r[0]), "=r"(r[1]), "=r"(r[2]), "=r"(r[3]) : "r"(addr));
}
__device__ __forceinline__ void mma16816(float* c, const uint32_t* a, const uint32_t* b) {
    asm volatile(
        "mma.sync.aligned.m16n8k16.row.col.f32.f16.f16.f32 "
        "{%0,%1,%2,%3}, {%4,%5,%6,%7}, {%8,%9}, {%0,%1,%2,%3};"
        : "+f"(c[0]), "+f"(c[1]), "+f"(c[2]), "+f"(c[3])
        : "r"(a[0]), "r"(a[1]), "r"(a[2]), "r"(a[3]), "r"(b[0]), "r"(b[1]));
}
__device__ __forceinline__ void stg128_cs(float* p, float4 v) {
    asm volatile("st.global.cs.v4.f32 [%0], {%1,%2,%3,%4};"
                 :: "l"(p), "f"(v.x), "f"(v.y), "f"(v.z), "f"(v.w) : "memory");
}

// ---------------- main kernel ----------------
__global__ void __launch_bounds__(256, 2)
rbf_logits_kernel(const float* __restrict__ x, const float* __restrict__ w,
                  float* __restrict__ out) {
    extern __shared__ char smem[];
    const uint32_t sb = smem_u32(smem);

    const int tid  = threadIdx.x;
    const int wid  = tid >> 5;
    const int lane = tid & 31;

    const int n_tile = blockIdx.x & (N_TILES - 1);   // consecutive CTAs share x tiles
    const int m_tile = blockIdx.x >> 5;              // N_TILES == 32
    const int n0 = n_tile * TN;

    float* wsq = reinterpret_cast<float*>(smem + OFF_WSQ);

    // x-tile loader: LDG f32 -> cvt fp16 -> STS (padded), fused x_sq
    auto load_x = [&](int m0, uint32_t a_off, float* xsq_buf) {
        const float4* xv = reinterpret_cast<const float4*>(x + (size_t)m0 * IN_DIM);
#pragma unroll
        for (int j = 0; j < 8; j++) {
            int idx4 = j * 256 + tid;          // 0..2047 (16 float4 per row)
            float4 v = xv[idx4];
            int row = idx4 >> 4;
            int c4  = idx4 & 15;

            uint32_t base = a_off + (uint32_t)(row * KP + c4 * 4) * 2;
            *reinterpret_cast<uint2*>(smem + base) =
                make_uint2(pack_h2(v.x, v.y), pack_h2(v.z, v.w));

            float p = v.x * v.x + v.y * v.y + v.z * v.z + v.w * v.w;
            p += __shfl_xor_sync(0xFFFFFFFFu, p, 8);
            p += __shfl_xor_sync(0xFFFFFFFFu, p, 4);
            p += __shfl_xor_sync(0xFFFFFFFFu, p, 2);
            p += __shfl_xor_sync(0xFFFFFFFFu, p, 1);
            if ((lane & 15) == 0) xsq_buf[row] = p;
        }
    };

    // ---- Load + convert W tile ONCE (fp16, COLUMN-PERMUTED rows), fused w_sq ----
    // Global col g -> tile row (g&0x70) | ((g&1)<<3) | ((g>>1)&7): interleaves two
    // adjacent n8 fragments so epilogue lanes own 4 consecutive global columns.
    {
        const float4* wv = reinterpret_cast<const float4*>(w + (size_t)n0 * IN_DIM);
#pragma unroll
        for (int j = 0; j < 8; j++) {
            int idx4 = j * 256 + tid;
            float4 v = wv[idx4];
            int row = idx4 >> 4;               // global n index in tile
            int c4  = idx4 & 15;
            int trow = (row & 0x70) | ((row & 1) << 3) | ((row >> 1) & 7);

            uint32_t base = OFF_B + (uint32_t)(trow * KP + c4 * 4) * 2;
            *reinterpret_cast<uint2*>(smem + base) =
                make_uint2(pack_h2(v.x, v.y), pack_h2(v.z, v.w));

            float p = v.x * v.x + v.y * v.y + v.z * v.z + v.w * v.w;
            p += __shfl_xor_sync(0xFFFFFFFFu, p, 8);
            p += __shfl_xor_sync(0xFFFFFFFFu, p, 4);
            p += __shfl_xor_sync(0xFFFFFFFFu, p, 2);
            p += __shfl_xor_sync(0xFFFFFFFFu, p, 1);
            if ((lane & 15) == 0) wsq[row] = p;   // GLOBAL col order
        }
    }

    // Prologue: first x tile into buffer 0
    load_x(m_tile * M_SUB * TM, OFF_A0, reinterpret_cast<float*>(smem + OFF_XSQ0));
    __syncthreads();

    // ---- Warp tiling: 8 warps = 4 (M) x 2 (N); warp tile = 32 x 64 ----
    const int m_warp = (wid >> 1) * 32;
    const int n_warp = (wid & 1) * 64;

    // A (row-major, m16k16 tiles): lane i -> row (i&15), k-half (i>>4)*8
    const uint32_t a_lane_off =
        ((uint32_t)(m_warp + (lane & 15)) * KP + ((lane >> 4) * 8)) * 2;
    // B ([n][k] row-major, NON-trans): mma B frag wants lane l -> (n=l>>2, k=(l&3)*2)
    const uint32_t b_addr = sb + OFF_B +
        ((uint32_t)(n_warp + ((lane >> 4) << 3) + (lane & 7)) * KP +
         (((lane >> 3) & 1) * 8)) * 2;

    const int q  = lane & 3;
    const int rl = lane >> 2;

#pragma unroll
    for (int sub = 0; sub < M_SUB; sub++) {
        const int p_buf = sub & 1;
        const uint32_t a_addr0 = sb + (p_buf ? OFF_A1 : OFF_A0) + a_lane_off;
        const uint32_t a_addr1 = a_addr0 + 16u * KP * 2;
        float* xsq = reinterpret_cast<float*>(smem + (p_buf ? OFF_XSQ1 : OFF_XSQ0));
        const int m0 = (m_tile * M_SUB + sub) * TM;

        float acc[2][8][4];
#pragma unroll
        for (int mt = 0; mt < 2; mt++)
#pragma unroll
            for (int nt = 0; nt < 8; nt++)
#pragma unroll
                for (int t = 0; t < 4; t++) acc[mt][nt][t] = 0.0f;

#pragma unroll
        for (int ks = 0; ks < 4; ks++) {          // K = 64 in steps of 16
            const uint32_t koff = (uint32_t)ks * 16 * 2;
            uint32_t a0[4], a1[4];
            ldsm_x4(a0, a_addr0 + koff);
            ldsm_x4(a1, a_addr1 + koff);
            uint32_t b[8][2];
#pragma unroll
            for (int pp = 0; pp < 4; pp++) {
                uint32_t r[4];
                ldsm_x4(r, b_addr + (uint32_t)pp * 16 * KP * 2 + koff);
                b[2 * pp][0] = r[0]; b[2 * pp][1] = r[1];
                b[2 * pp + 1][0] = r[2]; b[2 * pp + 1][1] = r[3];
            }
#pragma unroll
            for (int nt = 0; nt < 8; nt++) {
                mma16816(acc[0][nt], a0, b[nt]);
                mma16816(acc[1][nt], a1, b[nt]);
            }
        }

        // Grab xs before prefetch can start (reads this buffer's xsq)
        const float xs[4] = {
            xsq[m_warp +      rl],  xsq[m_warp +      rl + 8],
            xsq[m_warp + 16 + rl],  xsq[m_warp + 16 + rl + 8],
        };

        // ---- Prefetch next x tile into the other buffer; its LDG latency is
        // hidden under this iteration's epilogue FMAs + STGs. (Safe: other
        // buffer's last readers finished before the sync at end of sub-1.)
        if (sub + 1 < M_SUB) {
            load_x(m0 + TM, p_buf ? OFF_A0 : OFF_A1,
                   reinterpret_cast<float*>(smem + (p_buf ? OFF_XSQ0 : OFF_XSQ1)));
        }

        // ---- Epilogue: logits = 2*cross - x_sq - w_sq, float4 register stores ----
        // Permutation: frag 2p col c -> global p*16+2c, frag 2p+1 -> p*16+2c+1.
        // Lane q owns frag cols 2q,2q+1 of both => global cols p*16+4q..4q+3.
#pragma unroll
        for (int mt = 0; mt < 2; mt++) {
#pragma unroll
            for (int pp = 0; pp < 4; pp++) {
                const float* a = acc[mt][2 * pp];       // even global cols
                const float* b = acc[mt][2 * pp + 1];   // odd  global cols
                const int cbase = n_warp + pp * 16 + q * 4;
                const float4 wq = *reinterpret_cast<const float4*>(wsq + cbase);

                const size_t r0 = (size_t)(m0 + m_warp + mt * 16 + rl);
                const float xs0 = xs[mt * 2], xs1 = xs[mt * 2 + 1];

                float4 v0;
                v0.x = fmaf(2.0f, a[0], -(xs0 + wq.x));
                v0.y = fmaf(2.0f, b[0], -(xs0 + wq.y));
                v0.z = fmaf(2.0f, a[1], -(xs0 + wq.z));
                v0.w = fmaf(2.0f, b[1], -(xs0 + wq.w));
                stg128_cs(out + r0 * C_DIM + (n0 + cbase), v0);

                float4 v1;
                v1.x = fmaf(2.0f, a[2], -(xs1 + wq.x));
                v1.y = fmaf(2.0f, b[2], -(xs1 + wq.y));
                v1.z = fmaf(2.0f, a[3], -(xs1 + wq.z));
                v1.w = fmaf(2.0f, b[3], -(xs1 + wq.w));
                stg128_cs(out + (r0 + 8) * C_DIM + (n0 + cbase), v1);
            }
        }

        __syncthreads();   // next-buffer STS complete before next sub's LDSM
    }
}

extern "C" void kernel_launch(void* const* d_in, const int* in_sizes, int n_in,
                              void* d_out, int out_size) {
    const float* x = reinterpret_cast<const float*>(d_in[0]);
    const float* w = reinterpret_cast<const float*>(d_in[1]);
    // Defensive: identify by size (x has B*64 elements, w has C*64)
    if (n_in >= 2 && in_sizes[0] == C_DIM * IN_DIM && in_sizes[1] == B_DIM * IN_DIM) {
        const float* t = x; x = w; w = t;
    }
    float* out = reinterpret_cast<float*>(d_out);

    cudaFuncSetAttribute(rbf_logits_kernel,
                         cudaFuncAttributeMaxDynamicSharedMemorySize, SMEM_BYTES);
    rbf_logits_kernel<<<M_TILES * N_TILES, 256, SMEM_BYTES>>>(x, w, out);
}

// round 11
// speedup vs baseline: 1.0619x; 1.0619x over previous
#include <cuda_runtime.h>
#include <cuda_fp16.h>
#include <cstdint>

// Problem shape (fixed by dataset)
static constexpr int B_DIM   = 32768;
static constexpr int IN_DIM  = 64;
static constexpr int C_DIM   = 4096;

static constexpr int TM = 128;   // M tile per iteration
static constexpr int M_SUB = 4;  // M iterations per CTA (w tile reused 4x)
static constexpr int TN = 128;   // N tile per CTA
static constexpr int M_TILES = B_DIM / (TM * M_SUB);  // 64
static constexpr int N_TILES = C_DIM / TN;            // 32

// SMEM: A[2] = x fp16 [128 x 64k] double-buffered, B = w fp16 [128 x 64k]
// (column-PERMUTED). Row stride padded to 72 halfs (144 B) -> conflict-free ldmatrix.
static constexpr int KP       = 72;                    // padded K stride (elements)
static constexpr int A_BYTES  = 128 * KP * 2;          // 18432
static constexpr int OFF_XSQ0 = 0;                     // 128 f32
static constexpr int OFF_XSQ1 = 512;                   // 128 f32
static constexpr int OFF_WSQ  = 1024;                  // 128 f32 (GLOBAL col order)
static constexpr int OFF_A0   = 2048;
static constexpr int OFF_A1   = OFF_A0 + A_BYTES;      // 20480
static constexpr int OFF_B    = OFF_A1 + A_BYTES;      // 38912
static constexpr int SMEM_BYTES = OFF_B + A_BYTES;     // 57344

// ---------------- helpers ----------------
__device__ __forceinline__ uint32_t smem_u32(const void* p) {
    uint32_t a;
    asm("{ .reg .u64 t; cvta.to.shared.u64 t, %1; cvt.u32.u64 %0, t; }" : "=r"(a) : "l"(p));
    return a;
}
__device__ __forceinline__ uint32_t pack_h2(float a, float b) {
    __half2 v(__float2half_rn(a), __float2half_rn(b));
    return *reinterpret_cast<uint32_t*>(&v);
}
__device__ __forceinline__ void ldsm_x4(uint32_t* r, uint32_t addr) {
    asm volatile("ldmatrix.sync.aligned.m8n8.x4.shared.b16 {%0,%1,%2,%3}, [%4];"
                 : "=r"(r[0]), "=r"(r[1]), "=r"(r[2]), "=r"(r[3]) : "r"(addr));
}
__device__ __forceinline__ void mma16816(float* c, const uint32_t* a, const uint32_t* b) {
    asm volatile(
        "mma.sync.aligned.m16n8k16.row.col.f32.f16.f16.f32 "
        "{%0,%1,%2,%3}, {%4,%5,%6,%7}, {%8,%9}, {%0,%1,%2,%3};"
        : "+f"(c[0]), "+f"(c[1]), "+f"(c[2]), "+f"(c[3])
        : "r"(a[0]), "r"(a[1]), "r"(a[2]), "r"(a[3]), "r"(b[0]), "r"(b[1]));
}
__device__ __forceinline__ void stg128_cs(float* p, float4 v) {
    asm volatile("st.global.cs.v4.f32 [%0], {%1,%2,%3,%4};"
                 :: "l"(p), "f"(v.x), "f"(v.y), "f"(v.z), "f"(v.w) : "memory");
}

// ---------------- main kernel ----------------
__global__ void __launch_bounds__(256, 2)
rbf_logits_kernel(const float* __restrict__ x, const float* __restrict__ w,
                  float* __restrict__ out) {
    extern __shared__ char smem[];
    const uint32_t sb = smem_u32(smem);

    const int tid  = threadIdx.x;
    const int wid  = tid >> 5;
    const int lane = tid & 31;

    const int n_tile = blockIdx.x & (N_TILES - 1);   // consecutive CTAs share x tiles
    const int m_tile = blockIdx.x >> 5;              // N_TILES == 32
    const int n0 = n_tile * TN;

    float* wsq = reinterpret_cast<float*>(smem + OFF_WSQ);

    // x-tile loader: LDG f32 -> cvt fp16 -> STS (padded), fused x_sq
    auto load_x = [&](int m0, uint32_t a_off, float* xsq_buf) {
#pragma unroll
        for (int j = 0; j < 8; j++) {
            int idx4 = j * 256 + tid;          // 0..2047 (16 float4 per row)
            float4 v = reinterpret_cast<const float4*>(x + (size_t)m0 * IN_DIM)[idx4];
            int row = idx4 >> 4;
            int c4  = idx4 & 15;

            uint32_t base = a_off + (uint32_t)(row * KP + c4 * 4) * 2;
            *reinterpret_cast<uint2*>(smem + base) =
                make_uint2(pack_h2(v.x, v.y), pack_h2(v.z, v.w));

            float p = v.x * v.x + v.y * v.y + v.z * v.z + v.w * v.w;
            p += __shfl_xor_sync(0xFFFFFFFFu, p, 8);
            p += __shfl_xor_sync(0xFFFFFFFFu, p, 4);
            p += __shfl_xor_sync(0xFFFFFFFFu, p, 2);
            p += __shfl_xor_sync(0xFFFFFFFFu, p, 1);
            if ((lane & 15) == 0) xsq_buf[row] = p;
        }
    };

    // ---- Load + convert W tile ONCE (fp16, COLUMN-PERMUTED rows), fused w_sq ----
    // Global col g -> tile row (g&0x70) | ((g&1)<<3) | ((g>>1)&7): interleaves two
    // adjacent n8 fragments so epilogue lanes own 4 consecutive global columns.
    {
        const float4* wv = reinterpret_cast<const float4*>(w + (size_t)n0 * IN_DIM);
#pragma unroll
        for (int j = 0; j < 8; j++) {
            int idx4 = j * 256 + tid;
            float4 v = wv[idx4];
            int row = idx4 >> 4;               // global n index in tile
            int c4  = idx4 & 15;
            int trow = (row & 0x70) | ((row & 1) << 3) | ((row >> 1) & 7);

            uint32_t base = OFF_B + (uint32_t)(trow * KP + c4 * 4) * 2;
            *reinterpret_cast<uint2*>(smem + base) =
                make_uint2(pack_h2(v.x, v.y), pack_h2(v.z, v.w));

            float p = v.x * v.x + v.y * v.y + v.z * v.z + v.w * v.w;
            p += __shfl_xor_sync(0xFFFFFFFFu, p, 8);
            p += __shfl_xor_sync(0xFFFFFFFFu, p, 4);
            p += __shfl_xor_sync(0xFFFFFFFFu, p, 2);
            p += __shfl_xor_sync(0xFFFFFFFFu, p, 1);
            if ((lane & 15) == 0) wsq[row] = p;   // GLOBAL col order
        }
    }

    // Prologue: first x tile into buffer 0
    load_x(m_tile * M_SUB * TM, OFF_A0, reinterpret_cast<float*>(smem + OFF_XSQ0));
    __syncthreads();

    // ---- Warp tiling: 8 warps = 4 (M) x 2 (N); warp tile = 32 x 64 ----
    const int m_warp = (wid >> 1) * 32;
    const int n_warp = (wid & 1) * 64;

    // A (row-major, m16k16 tiles): lane i -> row (i&15), k-half (i>>4)*8
    const uint32_t a_lane_off =
        ((uint32_t)(m_warp + (lane & 15)) * KP + ((lane >> 4) * 8)) * 2;
    // B ([n][k] row-major, NON-trans): mma B frag wants lane l -> (n=l>>2, k=(l&3)*2)
    const uint32_t b_addr = sb + OFF_B +
        ((uint32_t)(n_warp + ((lane >> 4) << 3) + (lane & 7)) * KP +
         (((lane >> 3) & 1) * 8)) * 2;

    const int q  = lane & 3;
    const int rl = lane >> 2;

#pragma unroll 1
    for (int sub = 0; sub < M_SUB; sub++) {
        const int p_buf = sub & 1;
        const uint32_t a_addr0 = sb + (p_buf ? OFF_A1 : OFF_A0) + a_lane_off;
        const uint32_t a_addr1 = a_addr0 + 16u * KP * 2;
        float* xsq = reinterpret_cast<float*>(smem + (p_buf ? OFF_XSQ1 : OFF_XSQ0));
        const int m0 = (m_tile * M_SUB + sub) * TM;

        float acc[2][8][4];
#pragma unroll
        for (int mt = 0; mt < 2; mt++)
#pragma unroll
            for (int nt = 0; nt < 8; nt++)
#pragma unroll
                for (int t = 0; t < 4; t++) acc[mt][nt][t] = 0.0f;

#pragma unroll
        for (int ks = 0; ks < 4; ks++) {          // K = 64 in steps of 16
            const uint32_t koff = (uint32_t)ks * 16 * 2;
            uint32_t a0[4], a1[4];
            ldsm_x4(a0, a_addr0 + koff);
            ldsm_x4(a1, a_addr1 + koff);
            uint32_t b[8][2];
#pragma unroll
            for (int pp = 0; pp < 4; pp++) {
                uint32_t r[4];
                ldsm_x4(r, b_addr + (uint32_t)pp * 16 * KP * 2 + koff);
                b[2 * pp][0] = r[0]; b[2 * pp][1] = r[1];
                b[2 * pp + 1][0] = r[2]; b[2 * pp + 1][1] = r[3];
            }
#pragma unroll
            for (int nt = 0; nt < 8; nt++) {
                mma16816(acc[0][nt], a0, b[nt]);
                mma16816(acc[1][nt], a1, b[nt]);
            }
        }

        // Grab xs before prefetch overwrites nothing of this buffer (reads cur xsq)
        const float xs[4] = {
            xsq[m_warp +      rl],  xsq[m_warp +      rl + 8],
            xsq[m_warp + 16 + rl],  xsq[m_warp + 16 + rl + 8],
        };

        // ---- Prefetch next x tile into the other buffer; independent LDGs can be
        // hoisted/interleaved with epilogue FMAs + STGs by the scheduler. (Safe:
        // other buffer's last readers finished before the sync that ended sub-1.)
        if (sub + 1 < M_SUB) {
            load_x(m0 + TM, p_buf ? OFF_A0 : OFF_A1,
                   reinterpret_cast<float*>(smem + (p_buf ? OFF_XSQ0 : OFF_XSQ1)));
        }

        // ---- Epilogue: logits = 2*cross - x_sq - w_sq, float4 register stores ----
        // Permutation: frag 2p col c -> global p*16+2c, frag 2p+1 -> p*16+2c+1.
        // Lane q owns frag cols 2q,2q+1 of both => global cols p*16+4q..4q+3.
#pragma unroll
        for (int mt = 0; mt < 2; mt++) {
#pragma unroll
            for (int pp = 0; pp < 4; pp++) {
                const float* a = acc[mt][2 * pp];       // even global cols
                const float* b = acc[mt][2 * pp + 1];   // odd  global cols
                const int cbase = n_warp + pp * 16 + q * 4;
                const float4 wq = *reinterpret_cast<const float4*>(wsq + cbase);

                const size_t r0 = (size_t)(m0 + m_warp + mt * 16 + rl);
                const float xs0 = xs[mt * 2], xs1 = xs[mt * 2 + 1];

                float4 v0;
                v0.x = fmaf(2.0f, a[0], -(xs0 + wq.x));
                v0.y = fmaf(2.0f, b[0], -(xs0 + wq.y));
                v0.z = fmaf(2.0f, a[1], -(xs0 + wq.z));
                v0.w = fmaf(2.0f, b[1], -(xs0 + wq.w));
                stg128_cs(out + r0 * C_DIM + (n0 + cbase), v0);

                float4 v1;
                v1.x = fmaf(2.0f, a[2], -(xs1 + wq.x));
                v1.y = fmaf(2.0f, b[2], -(xs1 + wq.y));
                v1.z = fmaf(2.0f, a[3], -(xs1 + wq.z));
                v1.w = fmaf(2.0f, b[3], -(xs1 + wq.w));
                stg128_cs(out + (r0 + 8) * C_DIM + (n0 + cbase), v1);
            }
        }

        __syncthreads();   // publish prefetched buffer before next sub's LDSM
    }
}

extern "C" void kernel_launch(void* const* d_in, const int* in_sizes, int n_in,
                              void* d_out, int out_size) {
    const float* x = reinterpret_cast<const float*>(d_in[0]);
    const float* w = reinterpret_cast<const float*>(d_in[1]);
    // Defensive: identify by size (x has B*64 elements, w has C*64)
    if (n_in >= 2 && in_sizes[0] == C_DIM * IN_DIM && in_sizes[1] == B_DIM * IN_DIM) {
        const float* t = x; x = w; w = t;
    }
    float* out = reinterpret_cast<float*>(d_out);

    cudaFuncSetAttribute(rbf_logits_kernel,
                         cudaFuncAttributeMaxDynamicSharedMemorySize, SMEM_BYTES);
    rbf_logits_kernel<<<M_TILES * N_TILES, 256, SMEM_BYTES>>>(x, w, out);
}

// round 12
// speedup vs baseline: 1.2964x; 1.2208x over previous
#include <cuda_runtime.h>
#include <cuda_fp16.h>
#include <cstdint>

// Problem shape (fixed by dataset)
static constexpr int B_DIM   = 32768;
static constexpr int IN_DIM  = 64;
static constexpr int C_DIM   = 4096;

static constexpr int TM = 128;   // M tile per iteration
static constexpr int M_SUB = 4;  // M iterations per CTA (w tile reused 4x)
static constexpr int TN = 128;   // N tile per CTA
static constexpr int M_TILES = B_DIM / (TM * M_SUB);  // 64
static constexpr int N_TILES = C_DIM / TN;            // 32

// Preprocessed operands in device scratch (allowed: __device__ globals)
__device__ __align__(16) uint32_t x_h[B_DIM * (IN_DIM / 2)];   // fp16x2, 4 MB
__device__ __align__(16) uint32_t w_h[C_DIM * (IN_DIM / 2)];   // fp16x2, 512 KB
__device__ __align__(16) float    xsq_g[B_DIM];
__device__ __align__(16) float    wsq_g[C_DIM];

// SMEM: A[2] = x fp16 [128 x 64k] double-buffered, B = w fp16 [128 x 64k]
// (column-PERMUTED). Row stride padded to 72 halfs (144 B = 9x16B) -> conflict-free.
static constexpr int KP       = 72;                    // padded K stride (elements)
static constexpr int RB       = KP * 2;                // 144 bytes per row
static constexpr int A_BYTES  = 128 * RB;              // 18432
static constexpr int OFF_XSQ0 = 0;                     // 128 f32
static constexpr int OFF_XSQ1 = 512;                   // 128 f32
static constexpr int OFF_WSQ  = 1024;                  // 128 f32 (GLOBAL col order)
static constexpr int OFF_A0   = 2048;
static constexpr int OFF_A1   = OFF_A0 + A_BYTES;      // 20480
static constexpr int OFF_B    = OFF_A1 + A_BYTES;      // 38912
static constexpr int SMEM_BYTES = OFF_B + A_BYTES;     // 57344

// ---------------- helpers ----------------
__device__ __forceinline__ uint32_t smem_u32(const void* p) {
    uint32_t a;
    asm("{ .reg .u64 t; cvta.to.shared.u64 t, %1; cvt.u32.u64 %0, t; }" : "=r"(a) : "l"(p));
    return a;
}
__device__ __forceinline__ uint32_t pack_h2(float a, float b) {
    __half2 v(__float2half_rn(a), __float2half_rn(b));
    return *reinterpret_cast<uint32_t*>(&v);
}
__device__ __forceinline__ void cpasync16(uint32_t dst, const void* src) {
    asm volatile("cp.async.cg.shared.global [%0], [%1], 16;"
                 :: "r"(dst), "l"(src) : "memory");
}
__device__ __forceinline__ void cp_commit() {
    asm volatile("cp.async.commit_group;" ::: "memory");
}
__device__ __forceinline__ void cp_wait0() {
    asm volatile("cp.async.wait_group 0;" ::: "memory");
}
__device__ __forceinline__ void cp_wait1() {
    asm volatile("cp.async.wait_group 1;" ::: "memory");
}
__device__ __forceinline__ void ldsm_x4(uint32_t* r, uint32_t addr) {
    asm volatile("ldmatrix.sync.aligned.m8n8.x4.shared.b16 {%0,%1,%2,%3}, [%4];"
                 : "=r"(r[0]), "=r"(r[1]), "=r"(r[2]), "=r"(r[3]) : "r"(addr));
}
__device__ __forceinline__ void mma16816(float* c, const uint32_t* a, const uint32_t* b) {
    asm volatile(
        "mma.sync.aligned.m16n8k16.row.col.f32.f16.f16.f32 "
        "{%0,%1,%2,%3}, {%4,%5,%6,%7}, {%8,%9}, {%0,%1,%2,%3};"
        : "+f"(c[0]), "+f"(c[1]), "+f"(c[2]), "+f"(c[3])
        : "r"(a[0]), "r"(a[1]), "r"(a[2]), "r"(a[3]), "r"(b[0]), "r"(b[1]));
}
__device__ __forceinline__ void stg128_cs(float* p, float4 v) {
    asm volatile("st.global.cs.v4.f32 [%0], {%1,%2,%3,%4};"
                 :: "l"(p), "f"(v.x), "f"(v.y), "f"(v.z), "f"(v.w) : "memory");
}

// ---------------- pre-pass: f32 -> fp16 + squared norms ----------------
// Blocks 0..255: x rows [bid*128, +128). Blocks 256..287: w rows [(bid-256)*128, +128).
__global__ void __launch_bounds__(256)
prep_kernel(const float* __restrict__ x, const float* __restrict__ w) {
    const int bid  = blockIdx.x;
    const int tid  = threadIdx.x;
    const int lane = tid & 31;

    const bool is_x = (bid < 256);
    const size_t r0 = is_x ? (size_t)bid * 128 : (size_t)(bid - 256) * 128;
    const float4* src = reinterpret_cast<const float4*>((is_x ? x : w) + r0 * IN_DIM);
    uint32_t* dst_h  = (is_x ? x_h : w_h);
    float*    dst_sq = (is_x ? xsq_g : wsq_g);

#pragma unroll
    for (int j = 0; j < 8; j++) {
        int idx4 = j * 256 + tid;          // 0..2047 (16 float4 per row)
        float4 v = src[idx4];
        int row = idx4 >> 4;
        int c4  = idx4 & 15;

        *reinterpret_cast<uint2*>(dst_h + (r0 + row) * 32 + c4 * 2) =
            make_uint2(pack_h2(v.x, v.y), pack_h2(v.z, v.w));

        float p = v.x * v.x + v.y * v.y + v.z * v.z + v.w * v.w;
        p += __shfl_xor_sync(0xFFFFFFFFu, p, 8);
        p += __shfl_xor_sync(0xFFFFFFFFu, p, 4);
        p += __shfl_xor_sync(0xFFFFFFFFu, p, 2);
        p += __shfl_xor_sync(0xFFFFFFFFu, p, 1);
        if ((lane & 15) == 0) dst_sq[r0 + row] = p;
    }
}

// ---------------- main kernel ----------------
__global__ void __launch_bounds__(256, 2)
rbf_logits_kernel(float* __restrict__ out) {
    extern __shared__ char smem[];
    const uint32_t sb = smem_u32(smem);

    const int tid  = threadIdx.x;
    const int wid  = tid >> 5;
    const int lane = tid & 31;

    const int n_tile = blockIdx.x & (N_TILES - 1);   // consecutive CTAs share x tiles
    const int m_tile = blockIdx.x >> 5;              // N_TILES == 32
    const int n0 = n_tile * TN;

    // async x-tile loader: fp16 tile (1024 x 16B chunks) + xsq (32 chunks)
    auto load_x_async = [&](int m0, uint32_t a_off, uint32_t xsq_off) {
        const char* srcb = reinterpret_cast<const char*>(x_h) + (size_t)m0 * 128;
#pragma unroll
        for (int j = 0; j < 4; j++) {
            int idx = j * 256 + tid;       // 0..1023
            int row = idx >> 3;
            int c16 = idx & 7;
            cpasync16(sb + a_off + (uint32_t)(row * RB + c16 * 16),
                      srcb + (size_t)row * 128 + c16 * 16);
        }
        if (tid < 32)
            cpasync16(sb + xsq_off + (uint32_t)tid * 16, xsq_g + m0 + tid * 4);
    };

    // ---- Prologue group: W tile (PERMUTED rows) + wsq + first x tile ----
    // Global col g -> tile row (g&0x70) | ((g&1)<<3) | ((g>>1)&7): interleaves two
    // adjacent n8 fragments so epilogue lanes own 4 consecutive global columns.
    {
        const char* srcb = reinterpret_cast<const char*>(w_h) + (size_t)n0 * 128;
#pragma unroll
        for (int j = 0; j < 4; j++) {
            int idx = j * 256 + tid;
            int row = idx >> 3;
            int c16 = idx & 7;
            int trow = (row & 0x70) | ((row & 1) << 3) | ((row >> 1) & 7);
            cpasync16(sb + OFF_B + (uint32_t)(trow * RB + c16 * 16),
                      srcb + (size_t)row * 128 + c16 * 16);
        }
        if (tid < 32)
            cpasync16(sb + OFF_WSQ + (uint32_t)tid * 16, wsq_g + n0 + tid * 4);
        load_x_async(m_tile * M_SUB * TM, OFF_A0, OFF_XSQ0);
        cp_commit();
    }

    // ---- Warp tiling: 8 warps = 4 (M) x 2 (N); warp tile = 32 x 64 ----
    const int m_warp = (wid >> 1) * 32;
    const int n_warp = (wid & 1) * 64;

    // A (row-major, m16k16 tiles): lane i -> row (i&15), k-half (i>>4)*8
    const uint32_t a_lane_off =
        (uint32_t)(m_warp + (lane & 15)) * RB + ((lane >> 4) * 8) * 2;
    // B ([n][k] row-major, NON-trans): mma B frag wants lane l -> (n=l>>2, k=(l&3)*2)
    const uint32_t b_addr = sb + OFF_B +
        (uint32_t)(n_warp + ((lane >> 4) << 3) + (lane & 7)) * RB +
        (((lane >> 3) & 1) * 8) * 2;

    float* wsq = reinterpret_cast<float*>(smem + OFF_WSQ);
    const int q  = lane & 3;
    const int rl = lane >> 2;

#pragma unroll 1
    for (int sub = 0; sub < M_SUB; sub++) {
        const int p_buf = sub & 1;
        const uint32_t a_addr0 = sb + (p_buf ? OFF_A1 : OFF_A0) + a_lane_off;
        const uint32_t a_addr1 = a_addr0 + 16u * RB;
        float* xsq = reinterpret_cast<float*>(smem + (p_buf ? OFF_XSQ1 : OFF_XSQ0));
        const int m0 = (m_tile * M_SUB + sub) * TM;

        // Issue next tile's async group, then wait for the current one.
        if (sub + 1 < M_SUB) {
            load_x_async(m0 + TM, p_buf ? OFF_A0 : OFF_A1,
                         p_buf ? OFF_XSQ0 : OFF_XSQ1);
            cp_commit();
            cp_wait1();        // oldest (current buffer + initial w) complete
        } else {
            cp_wait0();
        }
        __syncthreads();       // all threads' async data visible

        float acc[2][8][4];
#pragma unroll
        for (int mt = 0; mt < 2; mt++)
#pragma unroll
            for (int nt = 0; nt < 8; nt++)
#pragma unroll
                for (int t = 0; t < 4; t++) acc[mt][nt][t] = 0.0f;

#pragma unroll
        for (int ks = 0; ks < 4; ks++) {          // K = 64 in steps of 16
            const uint32_t koff = (uint32_t)ks * 16 * 2;
            uint32_t a0[4], a1[4];
            ldsm_x4(a0, a_addr0 + koff);
            ldsm_x4(a1, a_addr1 + koff);
            uint32_t b[8][2];
#pragma unroll
            for (int pp = 0; pp < 4; pp++) {
                uint32_t r[4];
                ldsm_x4(r, b_addr + (uint32_t)pp * 16 * RB + koff);
                b[2 * pp][0] = r[0]; b[2 * pp][1] = r[1];
                b[2 * pp + 1][0] = r[2]; b[2 * pp + 1][1] = r[3];
            }
#pragma unroll
            for (int nt = 0; nt < 8; nt++) {
                mma16816(acc[0][nt], a0, b[nt]);
                mma16816(acc[1][nt], a1, b[nt]);
            }
        }

        const float xs[4] = {
            xsq[m_warp +      rl],  xsq[m_warp +      rl + 8],
            xsq[m_warp + 16 + rl],  xsq[m_warp + 16 + rl + 8],
        };

        // ---- Epilogue: logits = 2*cross - x_sq - w_sq, float4 register stores ----
        // Permutation: frag 2p col c -> global p*16+2c, frag 2p+1 -> p*16+2c+1.
        // Lane q owns frag cols 2q,2q+1 of both => global cols p*16+4q..4q+3.
#pragma unroll
        for (int mt = 0; mt < 2; mt++) {
#pragma unroll
            for (int pp = 0; pp < 4; pp++) {
                const float* a = acc[mt][2 * pp];       // even global cols
                const float* b = acc[mt][2 * pp + 1];   // odd  global cols
                const int cbase = n_warp + pp * 16 + q * 4;
                const float4 wq = *reinterpret_cast<const float4*>(wsq + cbase);

                const size_t r0 = (size_t)(m0 + m_warp + mt * 16 + rl);
                const float xs0 = xs[mt * 2], xs1 = xs[mt * 2 + 1];

                float4 v0;
                v0.x = fmaf(2.0f, a[0], -(xs0 + wq.x));
                v0.y = fmaf(2.0f, b[0], -(xs0 + wq.y));
                v0.z = fmaf(2.0f, a[1], -(xs0 + wq.z));
                v0.w = fmaf(2.0f, b[1], -(xs0 + wq.w));
                stg128_cs(out + r0 * C_DIM + (n0 + cbase), v0);

                float4 v1;
                v1.x = fmaf(2.0f, a[2], -(xs1 + wq.x));
                v1.y = fmaf(2.0f, b[2], -(xs1 + wq.y));
                v1.z = fmaf(2.0f, a[3], -(xs1 + wq.z));
                v1.w = fmaf(2.0f, b[3], -(xs1 + wq.w));
                stg128_cs(out + (r0 + 8) * C_DIM + (n0 + cbase), v1);
            }
        }

        __syncthreads();   // buf_cur reads done before next iter's cp.async into it
    }
}

extern "C" void kernel_launch(void* const* d_in, const int* in_sizes, int n_in,
                              void* d_out, int out_size) {
    const float* x = reinterpret_cast<const float*>(d_in[0]);
    const float* w = reinterpret_cast<const float*>(d_in[1]);
    // Defensive: identify by size (x has B*64 elements, w has C*64)
    if (n_in >= 2 && in_sizes[0] == C_DIM * IN_DIM && in_sizes[1] == B_DIM * IN_DIM) {
        const float* t = x; x = w; w = t;
    }
    float* out = reinterpret_cast<float*>(d_out);

    prep_kernel<<<288, 256>>>(x, w);

    cudaFuncSetAttribute(rbf_logits_kernel,
                         cudaFuncAttributeMaxDynamicSharedMemorySize, SMEM_BYTES);
    rbf_logits_kernel<<<M_TILES * N_TILES, 256, SMEM_BYTES>>>(out);
}

// round 13
// speedup vs baseline: 1.3121x; 1.0121x over previous
#include <cuda_runtime.h>
#include <cuda_fp16.h>
#include <cstdint>

// Problem shape (fixed by dataset)
static constexpr int B_DIM   = 32768;
static constexpr int IN_DIM  = 64;
static constexpr int C_DIM   = 4096;

static constexpr int TM = 64;    // M tile per iteration
static constexpr int M_SUB = 4;  // M iterations per CTA (w tile reused 4x)
static constexpr int TN = 128;   // N tile per CTA
static constexpr int M_TILES = B_DIM / (TM * M_SUB);  // 128
static constexpr int N_TILES = C_DIM / TN;            // 32

// Preprocessed operands in device scratch (allowed: __device__ globals)
__device__ __align__(16) uint32_t x_h[B_DIM * (IN_DIM / 2)];   // fp16x2, 4 MB
__device__ __align__(16) uint32_t w_h[C_DIM * (IN_DIM / 2)];   // fp16x2, 512 KB
__device__ __align__(16) float    xsq_g[B_DIM];
__device__ __align__(16) float    wsq_g[C_DIM];

// SMEM: A[2] = x fp16 [64 x 64k] double-buffered, B = w fp16 [128 x 64k]
// (column-PERMUTED). Row stride padded to 72 halfs (144 B = 9x16B) -> conflict-free.
static constexpr int KP       = 72;                    // padded K stride (elements)
static constexpr int RB       = KP * 2;                // 144 bytes per row
static constexpr int A_BYTES  = TM * RB;               // 9216
static constexpr int B_BYTES  = 128 * RB;              // 18432
static constexpr int OFF_XSQ0 = 0;                     // 64 f32
static constexpr int OFF_XSQ1 = 256;                   // 64 f32
static constexpr int OFF_WSQ  = 512;                   // 128 f32 (GLOBAL col order)
static constexpr int OFF_A0   = 1024;
static constexpr int OFF_A1   = OFF_A0 + A_BYTES;      // 10240
static constexpr int OFF_B    = OFF_A1 + A_BYTES;      // 19456
static constexpr int SMEM_BYTES = OFF_B + B_BYTES;     // 37888

// ---------------- helpers ----------------
__device__ __forceinline__ uint32_t smem_u32(const void* p) {
    uint32_t a;
    asm("{ .reg .u64 t; cvta.to.shared.u64 t, %1; cvt.u32.u64 %0, t; }" : "=r"(a) : "l"(p));
    return a;
}
__device__ __forceinline__ uint32_t pack_h2(float a, float b) {
    __half2 v(__float2half_rn(a), __float2half_rn(b));
    return *reinterpret_cast<uint32_t*>(&v);
}
__device__ __forceinline__ void cpasync16(uint32_t dst, const void* src) {
    asm volatile("cp.async.cg.shared.global [%0], [%1], 16;"
                 :: "r"(dst), "l"(src) : "memory");
}
__device__ __forceinline__ void cp_commit() {
    asm volatile("cp.async.commit_group;" ::: "memory");
}
__device__ __forceinline__ void cp_wait0() {
    asm volatile("cp.async.wait_group 0;" ::: "memory");
}
__device__ __forceinline__ void cp_wait1() {
    asm volatile("cp.async.wait_group 1;" ::: "memory");
}
__device__ __forceinline__ void ldsm_x4(uint32_t* r, uint32_t addr) {
    asm volatile("ldmatrix.sync.aligned.m8n8.x4.shared.b16 {%0,%1,%2,%3}, [%4];"
                 : "=r"(r[0]), "=r"(r[1]), "=r"(r[2]), "=r"(r[3]) : "r"(addr));
}
__device__ __forceinline__ void mma16816(float* c, const uint32_t* a, const uint32_t* b) {
    asm volatile(
        "mma.sync.aligned.m16n8k16.row.col.f32.f16.f16.f32 "
        "{%0,%1,%2,%3}, {%4,%5,%6,%7}, {%8,%9}, {%0,%1,%2,%3};"
        : "+f"(c[0]), "+f"(c[1]), "+f"(c[2]), "+f"(c[3])
        : "r"(a[0]), "r"(a[1]), "r"(a[2]), "r"(a[3]), "r"(b[0]), "r"(b[1]));
}
__device__ __forceinline__ void stg128_cs(float* p, float4 v) {
    asm volatile("st.global.cs.v4.f32 [%0], {%1,%2,%3,%4};"
                 :: "l"(p), "f"(v.x), "f"(v.y), "f"(v.z), "f"(v.w) : "memory");
}

// ---------------- pre-pass: f32 -> fp16 + squared norms ----------------
// Blocks 0..255: x rows [bid*128, +128). Blocks 256..287: w rows [(bid-256)*128, +128).
__global__ void __launch_bounds__(256)
prep_kernel(const float* __restrict__ x, const float* __restrict__ w) {
    const int bid  = blockIdx.x;
    const int tid  = threadIdx.x;
    const int lane = tid & 31;

    const bool is_x = (bid < 256);
    const size_t r0 = is_x ? (size_t)bid * 128 : (size_t)(bid - 256) * 128;
    const float4* src = reinterpret_cast<const float4*>((is_x ? x : w) + r0 * IN_DIM);
    uint32_t* dst_h  = (is_x ? x_h : w_h);
    float*    dst_sq = (is_x ? xsq_g : wsq_g);

#pragma unroll
    for (int j = 0; j < 8; j++) {
        int idx4 = j * 256 + tid;          // 0..2047 (16 float4 per row)
        float4 v = src[idx4];
        int row = idx4 >> 4;
        int c4  = idx4 & 15;

        *reinterpret_cast<uint2*>(dst_h + (r0 + row) * 32 + c4 * 2) =
            make_uint2(pack_h2(v.x, v.y), pack_h2(v.z, v.w));

        float p = v.x * v.x + v.y * v.y + v.z * v.z + v.w * v.w;
        p += __shfl_xor_sync(0xFFFFFFFFu, p, 8);
        p += __shfl_xor_sync(0xFFFFFFFFu, p, 4);
        p += __shfl_xor_sync(0xFFFFFFFFu, p, 2);
        p += __shfl_xor_sync(0xFFFFFFFFu, p, 1);
        if ((lane & 15) == 0) dst_sq[r0 + row] = p;
    }
}

// ---------------- main kernel: 128 threads, 4 CTAs/SM ----------------
__global__ void __launch_bounds__(128, 4)
rbf_logits_kernel(float* __restrict__ out) {
    extern __shared__ char smem[];
    const uint32_t sb = smem_u32(smem);

    const int tid  = threadIdx.x;
    const int wid  = tid >> 5;
    const int lane = tid & 31;

    const int n_tile = blockIdx.x & (N_TILES - 1);   // consecutive CTAs share x tiles
    const int m_tile = blockIdx.x >> 5;              // N_TILES == 32
    const int n0 = n_tile * TN;

    // async x-tile loader: fp16 tile (512 x 16B chunks) + xsq (16 chunks)
    auto load_x_async = [&](int m0, uint32_t a_off, uint32_t xsq_off) {
        const char* srcb = reinterpret_cast<const char*>(x_h) + (size_t)m0 * 128;
#pragma unroll
        for (int j = 0; j < 4; j++) {
            int idx = j * 128 + tid;       // 0..511
            int row = idx >> 3;
            int c16 = idx & 7;
            cpasync16(sb + a_off + (uint32_t)(row * RB + c16 * 16),
                      srcb + (size_t)row * 128 + c16 * 16);
        }
        if (tid < 16)
            cpasync16(sb + xsq_off + (uint32_t)tid * 16, xsq_g + m0 + tid * 4);
    };

    // ---- Prologue group: W tile (PERMUTED rows) + wsq + first x tile ----
    // Global col g -> tile row (g&0x70) | ((g&1)<<3) | ((g>>1)&7): interleaves two
    // adjacent n8 fragments so epilogue lanes own 4 consecutive global columns.
    {
        const char* srcb = reinterpret_cast<const char*>(w_h) + (size_t)n0 * 128;
#pragma unroll
        for (int j = 0; j < 8; j++) {
            int idx = j * 128 + tid;       // 0..1023
            int row = idx >> 3;
            int c16 = idx & 7;
            int trow = (row & 0x70) | ((row & 1) << 3) | ((row >> 1) & 7);
            cpasync16(sb + OFF_B + (uint32_t)(trow * RB + c16 * 16),
                      srcb + (size_t)row * 128 + c16 * 16);
        }
        if (tid < 32)
            cpasync16(sb + OFF_WSQ + (uint32_t)tid * 16, wsq_g + n0 + tid * 4);
        load_x_async(m_tile * M_SUB * TM, OFF_A0, OFF_XSQ0);
        cp_commit();
    }

    // ---- Warp tiling: 4 warps = 2 (M) x 2 (N); warp tile = 32 x 64 ----
    const int m_warp = (wid >> 1) * 32;
    const int n_warp = (wid & 1) * 64;

    // A (row-major, m16k16 tiles): lane i -> row (i&15), k-half (i>>4)*8
    const uint32_t a_lane_off =
        (uint32_t)(m_warp + (lane & 15)) * RB + ((lane >> 4) * 8) * 2;
    // B ([n][k] row-major, NON-trans): mma B frag wants lane l -> (n=l>>2, k=(l&3)*2)
    const uint32_t b_addr = sb + OFF_B +
        (uint32_t)(n_warp + ((lane >> 4) << 3) + (lane & 7)) * RB +
        (((lane >> 3) & 1) * 8) * 2;

    float* wsq = reinterpret_cast<float*>(smem + OFF_WSQ);
    const int q  = lane & 3;
    const int rl = lane >> 2;

#pragma unroll 1
    for (int sub = 0; sub < M_SUB; sub++) {
        const int p_buf = sub & 1;
        const uint32_t a_addr0 = sb + (p_buf ? OFF_A1 : OFF_A0) + a_lane_off;
        const uint32_t a_addr1 = a_addr0 + 16u * RB;
        float* xsq = reinterpret_cast<float*>(smem + (p_buf ? OFF_XSQ1 : OFF_XSQ0));
        const int m0 = (m_tile * M_SUB + sub) * TM;

        // Issue next tile's async group, then wait for the current one.
        if (sub + 1 < M_SUB) {
            load_x_async(m0 + TM, p_buf ? OFF_A0 : OFF_A1,
                         p_buf ? OFF_XSQ0 : OFF_XSQ1);
            cp_commit();
            cp_wait1();        // oldest (current buffer + prologue) complete
        } else {
            cp_wait0();
        }
        __syncthreads();       // all threads' async data visible

        float acc[2][8][4];
#pragma unroll
        for (int mt = 0; mt < 2; mt++)
#pragma unroll
            for (int nt = 0; nt < 8; nt++)
#pragma unroll
                for (int t = 0; t < 4; t++) acc[mt][nt][t] = 0.0f;

#pragma unroll
        for (int ks = 0; ks < 4; ks++) {          // K = 64 in steps of 16
            const uint32_t koff = (uint32_t)ks * 16 * 2;
            uint32_t a0[4], a1[4];
            ldsm_x4(a0, a_addr0 + koff);
            ldsm_x4(a1, a_addr1 + koff);
            uint32_t b[8][2];
#pragma unroll
            for (int pp = 0; pp < 4; pp++) {
                uint32_t r[4];
                ldsm_x4(r, b_addr + (uint32_t)pp * 16 * RB + koff);
                b[2 * pp][0] = r[0]; b[2 * pp][1] = r[1];
                b[2 * pp + 1][0] = r[2]; b[2 * pp + 1][1] = r[3];
            }
#pragma unroll
            for (int nt = 0; nt < 8; nt++) {
                mma16816(acc[0][nt], a0, b[nt]);
                mma16816(acc[1][nt], a1, b[nt]);
            }
        }

        const float xs[4] = {
            xsq[m_warp +      rl],  xsq[m_warp +      rl + 8],
            xsq[m_warp + 16 + rl],  xsq[m_warp + 16 + rl + 8],
        };

        // ---- Epilogue: logits = 2*cross - x_sq - w_sq, float4 register stores ----
        // Permutation: frag 2p col c -> global p*16+2c, frag 2p+1 -> p*16+2c+1.
        // Lane q owns frag cols 2q,2q+1 of both => global cols p*16+4q..4q+3.
#pragma unroll
        for (int mt = 0; mt < 2; mt++) {
#pragma unroll
            for (int pp = 0; pp < 4; pp++) {
                const float* a = acc[mt][2 * pp];       // even global cols
                const float* b = acc[mt][2 * pp + 1];   // odd  global cols
                const int cbase = n_warp + pp * 16 + q * 4;
                const float4 wq = *reinterpret_cast<const float4*>(wsq + cbase);

                const size_t r0 = (size_t)(m0 + m_warp + mt * 16 + rl);
                const float xs0 = xs[mt * 2], xs1 = xs[mt * 2 + 1];

                float4 v0;
                v0.x = fmaf(2.0f, a[0], -(xs0 + wq.x));
                v0.y = fmaf(2.0f, b[0], -(xs0 + wq.y));
                v0.z = fmaf(2.0f, a[1], -(xs0 + wq.z));
                v0.w = fmaf(2.0f, b[1], -(xs0 + wq.w));
                stg128_cs(out + r0 * C_DIM + (n0 + cbase), v0);

                float4 v1;
                v1.x = fmaf(2.0f, a[2], -(xs1 + wq.x));
                v1.y = fmaf(2.0f, b[2], -(xs1 + wq.y));
                v1.z = fmaf(2.0f, a[3], -(xs1 + wq.z));
                v1.w = fmaf(2.0f, b[3], -(xs1 + wq.w));
                stg128_cs(out + (r0 + 8) * C_DIM + (n0 + cbase), v1);
            }
        }

        __syncthreads();   // buf_cur reads done before next iter's cp.async into it
    }
}

extern "C" void kernel_launch(void* const* d_in, const int* in_sizes, int n_in,
                              void* d_out, int out_size) {
    const float* x = reinterpret_cast<const float*>(d_in[0]);
    const float* w = reinterpret_cast<const float*>(d_in[1]);
    // Defensive: identify by size (x has B*64 elements, w has C*64)
    if (n_in >= 2 && in_sizes[0] == C_DIM * IN_DIM && in_sizes[1] == B_DIM * IN_DIM) {
        const float* t = x; x = w; w = t;
    }
    float* out = reinterpret_cast<float*>(d_out);

    prep_kernel<<<288, 256>>>(x, w);

    cudaFuncSetAttribute(rbf_logits_kernel,
                         cudaFuncAttributeMaxDynamicSharedMemorySize, SMEM_BYTES);
    rbf_logits_kernel<<<M_TILES * N_TILES, 128, SMEM_BYTES>>>(out);
}